// round 13
// baseline (speedup 1.0000x reference)
#include <cuda_runtime.h>
#include <cstdint>

#define N_NODES 8192
#define DIM 256
#define SPLIT 2
#define KSPAN (N_NODES / SPLIT)   // 4096
#define BK 32
#define NCH (KSPAN / BK)          // 128 iters per CTA
#define BM 64
#define NCHUNK_TOT (N_NODES / BK) // 256 packed V chunks
#define LOG2E 1.4426950408889634f

// ---- device scratch (static only) ----
__device__ float  g_At[N_NODES * DIM];          // tf32-rounded gemm A operand
__device__ float2 g_Wp[(DIM / BK) * 16 * 256];  // packed tf32 W pairs (256 KB)
__device__ float2 g_Vp[NCHUNK_TOT * 16 * 256];  // packed tf32 V pairs (8 MB)
__device__ float  g_h1[N_NODES * DIM];
__device__ float  g_Dp[SPLIT][N_NODES * DIM];   // split-K partial numerators
__device__ float  g_Zp[SPLIT][N_NODES];         // split-K partial Z
__device__ float  g_sL[N_NODES];                // s * log2(e)
__device__ float  g_dL[N_NODES];                // d * log2(e)

__device__ __forceinline__ float tf32r(float x) {
    uint32_t u;
    asm("cvt.rna.tf32.f32 %0, %1;" : "=r"(u) : "f"(x));
    return __uint_as_float(u);
}
__device__ __forceinline__ float ex2(float x) {
    float r;
    asm("ex2.approx.f32 %0, %1;" : "=f"(r) : "f"(x));
    return r;
}
__device__ __forceinline__ void mma_tf32(float4& c, const uint32_t a[4],
                                         uint32_t b0, uint32_t b1) {
    asm volatile(
        "mma.sync.aligned.m16n8k8.row.col.f32.tf32.tf32.f32 "
        "{%0,%1,%2,%3}, {%4,%5,%6,%7}, {%8,%9}, {%0,%1,%2,%3};"
        : "+f"(c.x), "+f"(c.y), "+f"(c.z), "+f"(c.w)
        : "r"(a[0]), "r"(a[1]), "r"(a[2]), "r"(a[3]), "r"(b0), "r"(b1));
}
__device__ __forceinline__ void cp_async16(uint32_t dst, const void* src) {
    asm volatile("cp.async.cg.shared.global [%0], [%1], 16;" :: "r"(dst), "l"(src));
}

// ---------------------------------------------------------------------------
// apack: tf32-round A operand elementwise (layer-1 input only)
// ---------------------------------------------------------------------------
__global__ void __launch_bounds__(256) apack(const float* __restrict__ A,
                                             float* __restrict__ At) {
    int idx = blockIdx.x * 256 + threadIdx.x;
    float4 v = ((const float4*)A)[idx];
    ((float4*)At)[idx] = make_float4(tf32r(v.x), tf32r(v.y), tf32r(v.z), tf32r(v.w));
}

// ---------------------------------------------------------------------------
// wpack: Wp[(c*16+w)*256+n] = (tf32(W[j0][n]), tf32(W[j0+4][n]))
// ---------------------------------------------------------------------------
__global__ void __launch_bounds__(256) wpack(const float* __restrict__ W,
                                             float2* __restrict__ Wp) {
    const int c = blockIdx.x;
    const int t = threadIdx.x;
    #pragma unroll
    for (int w = 0; w < 16; w++) {
        int j0 = c * 32 + (w >> 2) * 8 + (w & 3);
        float v0 = W[(size_t)j0 * DIM + t];
        float v1 = W[(size_t)(j0 + 4) * DIM + t];
        Wp[(size_t)(c * 16 + w) * 256 + t] = make_float2(tf32r(v0), tf32r(v1));
    }
}

// ---------------------------------------------------------------------------
// Tensor-core GEMM Wh = At @ W, FUSED epilogue (unchanged from R12):
//   parks the 64x256 Wh tile in smem, emits packed Vp + sL/dL directly.
// ---------------------------------------------------------------------------
#define GA_STRIDE 36
#define GA_FLOATS (64 * GA_STRIDE)          // 2304
#define GVROW 520
#define GW_FLOATS (16 * GVROW)              // 8320
#define GMAIN_FLOATS (2 * GA_FLOATS + 2 * GW_FLOATS)   // 21248 floats
#define WS 260                               // epilogue tile stride
#define GSMEM_BYTES ((GMAIN_FLOATS + 2 * 256) * 4 + 16)

__global__ void __launch_bounds__(256, 2) gemm_tc(const float* __restrict__ At,
                                                  const float2* __restrict__ Wp,
                                                  float2* __restrict__ Vp,
                                                  const float* __restrict__ a_src,
                                                  const float* __restrict__ a_dst) {
    extern __shared__ float smem[];
    float* sA = smem;
    float* sW = smem + 2 * GA_FLOATS;
    float* sas = smem + GMAIN_FLOATS;
    float* sad = sas + 256;

    const int t = threadIdx.x;
    const int lane = t & 31;
    const int warp = t >> 5;
    const int warpM = warp >> 2;
    const int warpN = warp & 3;
    const int gid = lane >> 2;
    const int tig = lane & 3;
    const int i0 = blockIdx.x * 64;

    const uint32_t sA_u32 = (uint32_t)__cvta_generic_to_shared(sA);
    const uint32_t sW_u32 = (uint32_t)__cvta_generic_to_shared(sW);

    sas[t] = a_src[t];
    sad[t] = a_dst[t];

    float4 acc[2][8];
    #pragma unroll
    for (int m = 0; m < 2; m++)
        #pragma unroll
        for (int n = 0; n < 8; n++) acc[m][n] = make_float4(0.f, 0.f, 0.f, 0.f);

    auto stage = [&](int buf, int ch) {
        #pragma unroll
        for (int w = 0; w < 2; w++) {
            int qid = t + 256 * w;
            int rp = qid >> 3, u = qid & 7;
            cp_async16(sA_u32 + buf * (GA_FLOATS * 4) + rp * (GA_STRIDE * 4) + u * 16,
                       At + (size_t)(i0 + rp) * DIM + ch * 32 + u * 4);
        }
        const char* gsrc = (const char*)(Wp + (size_t)ch * 16 * 256);
        #pragma unroll
        for (int w = 0; w < 8; w++) {
            int qid = t + 256 * w;
            int rp = qid >> 7;
            int off = (qid & 127) * 16;
            cp_async16(sW_u32 + buf * (GW_FLOATS * 4) + rp * (GVROW * 4) + off,
                       gsrc + qid * 16);
        }
        asm volatile("cp.async.commit_group;" ::: "memory");
    };

    stage(0, 0);

    #pragma unroll
    for (int it = 0; it < 8; ++it) {
        const int cur = it & 1, nxt = cur ^ 1;
        asm volatile("cp.async.wait_group 0;" ::: "memory");
        __syncthreads();
        if (it + 1 < 8) stage(nxt, it + 1);

        const float* A = sA + cur * GA_FLOATS;
        const float* Wb = sW + cur * GW_FLOATS;

        #pragma unroll
        for (int kc = 0; kc < 4; kc++) {
            uint32_t a[2][4];
            #pragma unroll
            for (int mt = 0; mt < 2; mt++) {
                const int r = warpM * 32 + mt * 16 + gid;
                const int c = kc * 8 + tig;
                a[mt][0] = __float_as_uint(A[r * GA_STRIDE + c]);
                a[mt][1] = __float_as_uint(A[(r + 8) * GA_STRIDE + c]);
                a[mt][2] = __float_as_uint(A[r * GA_STRIDE + c + 4]);
                a[mt][3] = __float_as_uint(A[(r + 8) * GA_STRIDE + c + 4]);
            }
            const float* vrow = Wb + (kc * 4 + tig) * GVROW;
            #pragma unroll
            for (int nt = 0; nt < 8; nt++) {
                const int n = warpN * 64 + nt * 8 + gid;
                float2 b = *(const float2*)&vrow[n * 2];
                mma_tf32(acc[0][nt], a[0], __float_as_uint(b.x), __float_as_uint(b.y));
                mma_tf32(acc[1][nt], a[1], __float_as_uint(b.x), __float_as_uint(b.y));
            }
        }
        __syncthreads();
    }

    // ---- epilogue: park tile in smem ----
    float* S = smem;                          // [64][WS]
    #pragma unroll
    for (int mt = 0; mt < 2; mt++) {
        const int r0 = warpM * 32 + mt * 16 + gid;
        const int r1 = r0 + 8;
        #pragma unroll
        for (int nt = 0; nt < 8; nt++) {
            const int col = warpN * 64 + nt * 8 + 2 * tig;
            float4 c = acc[mt][nt];
            S[r0 * WS + col] = c.x; S[r0 * WS + col + 1] = c.y;
            S[r1 * WS + col] = c.z; S[r1 * WS + col + 1] = c.w;
        }
    }
    __syncthreads();

    #pragma unroll
    for (int half = 0; half < 2; half++) {
        const int chunk = (i0 >> 5) + half;
        #pragma unroll
        for (int w = 0; w < 16; w++) {
            int jl = half * 32 + (w >> 2) * 8 + (w & 3);
            float v0 = S[jl * WS + t];
            float v1 = S[(jl + 4) * WS + t];
            Vp[(size_t)(chunk * 16 + w) * 256 + t] = make_float2(tf32r(v0), tf32r(v1));
        }
    }

    #pragma unroll
    for (int rr = 0; rr < 8; rr++) {
        const int rl = warp * 8 + rr;
        float ps = 0.f, pd = 0.f;
        #pragma unroll
        for (int c = lane; c < 256; c += 32) {
            float v = S[rl * WS + c];
            ps = fmaf(v, sas[c], ps);
            pd = fmaf(v, sad[c], pd);
        }
        #pragma unroll
        for (int o = 16; o > 0; o >>= 1) {
            ps += __shfl_down_sync(0xffffffffu, ps, o);
            pd += __shfl_down_sync(0xffffffffu, pd, o);
        }
        if (lane == 0) {
            g_sL[i0 + rl] = ps * LOG2E;
            g_dL[i0 + rl] = pd * LOG2E;
        }
    }
}

// ---------------------------------------------------------------------------
// Fused attention * Wh. Change vs R12 champion: P tile stored PAIR-PACKED
// as (c, c+4) float2 — A fragment = 2x LDS.64 instead of 4x LDS.32.
// Row stride 20 float2: consumer LDS.64 conflict-free (4*gid+tig mod 16).
// Everything else identical (int4 adj, ex2 P, split-K=2, 2 CTAs/SM).
// ---------------------------------------------------------------------------
#define PA2_STRIDE 20                        // float2 units per row
#define PA2_F2 (64 * PA2_STRIDE)             // 1280 float2 per buffer
#define VROW 520
#define VP_FLOATS (16 * VROW)                // 8320
#define SMEM_BYTES (2 * PA2_F2 * 8 + 2 * VP_FLOATS * 4 + 16)

__global__ void __launch_bounds__(256, 2) gat_mma(const float2* __restrict__ Vp,
                                                  const int* __restrict__ adj,
                                                  float* __restrict__ Dp,
                                                  float* __restrict__ Zp) {
    extern __shared__ float smem[];
    float2* spA2 = (float2*)smem;               // [2][PA2_F2]
    float* svp = smem + 2 * PA2_F2 * 2;         // [2][VP_FLOATS]

    const int t = threadIdx.x;
    const int lane = t & 31;
    const int warp = t >> 5;
    const int warpM = warp >> 2;            // 0..1
    const int warpN = warp & 3;             // 0..3
    const int gid = lane >> 2;              // 0..7
    const int tig = lane & 3;               // 0..3
    const int i0 = blockIdx.x * BM;
    const int split = blockIdx.y;
    const int ch0 = split * (NCHUNK_TOT / SPLIT);

    Dp += (size_t)split * N_NODES * DIM;
    Zp += (size_t)split * N_NODES;

    // P producer: thread -> row pr (0..63), k-chunk kc0 = t&3 (cols kb..kb+7)
    const int pr = t >> 2;
    const int kc0 = t & 3;
    const int kb = kc0 * 8;
    const float sL_r = g_sL[i0 + pr];
    const int* adjrow = adj + (size_t)(i0 + pr) * N_NODES + split * KSPAN;
    const float* dbase = g_dL + split * KSPAN;

    float4 acc[2][8];
    #pragma unroll
    for (int m = 0; m < 2; m++)
        #pragma unroll
        for (int n = 0; n < 8; n++) acc[m][n] = make_float4(0.f, 0.f, 0.f, 0.f);
    float zacc = 0.f;

    const uint32_t sv_u32 = (uint32_t)__cvta_generic_to_shared(svp);

    auto produce_P = [&](float2* buf, const int4 aj[2], const float4 dv[2]) {
        const float dj[8] = {dv[0].x, dv[0].y, dv[0].z, dv[0].w,
                             dv[1].x, dv[1].y, dv[1].z, dv[1].w};
        const int mk[8] = {aj[0].x, aj[0].y, aj[0].z, aj[0].w,
                           aj[1].x, aj[1].y, aj[1].z, aj[1].w};
        float p[8];
        #pragma unroll
        for (int q = 0; q < 8; q++) {
            float t2 = sL_r + dj[q];
            float e = ex2(fmaxf(t2, 0.2f * t2));
            p[q] = mk[q] ? e : 0.f;
        }
        zacc += ((p[0] + p[1]) + (p[2] + p[3])) + ((p[4] + p[5]) + (p[6] + p[7]));
        // pair-packed: entry u = kc0*4+q holds (col kb+q, col kb+q+4)
        float2* dst = buf + pr * PA2_STRIDE + kc0 * 4;
        *(float4*)&dst[0] = make_float4(tf32r(p[0]), tf32r(p[4]), tf32r(p[1]), tf32r(p[5]));
        *(float4*)&dst[2] = make_float4(tf32r(p[2]), tf32r(p[6]), tf32r(p[3]), tf32r(p[7]));
    };

    auto issue_V = [&](int buf, int chunk) {
        const char* gsrc = (const char*)(Vp + (size_t)chunk * 16 * 256);
        uint32_t base = sv_u32 + buf * (VP_FLOATS * 4);
        #pragma unroll
        for (int w = 0; w < 8; w++) {
            int qid = t + 256 * w;
            int rp = qid >> 7;
            int off = (qid & 127) * 16;
            cp_async16(base + rp * (VROW * 4) + off, gsrc + qid * 16);
        }
        asm volatile("cp.async.commit_group;" ::: "memory");
    };

    {
        int4 aj[2]; float4 dv[2];
        aj[0] = *(const int4*)&adjrow[kb];
        aj[1] = *(const int4*)&adjrow[kb + 4];
        dv[0] = *(const float4*)&dbase[kb];
        dv[1] = *(const float4*)&dbase[kb + 4];
        produce_P(spA2, aj, dv);
        issue_V(0, ch0);
    }

    for (int it = 0; it < NCH; ++it) {
        const int cur = it & 1, nxt = cur ^ 1;
        const bool more = (it + 1 < NCH);

        int4 aj[2]; float4 dv[2];
        if (more) {
            const int jc = (it + 1) * BK;
            aj[0] = *(const int4*)&adjrow[jc + kb];
            aj[1] = *(const int4*)&adjrow[jc + kb + 4];
            dv[0] = *(const float4*)&dbase[jc + kb];
            dv[1] = *(const float4*)&dbase[jc + kb + 4];
        }

        asm volatile("cp.async.wait_group 0;" ::: "memory");
        __syncthreads();

        if (more) issue_V(nxt, ch0 + it + 1);

        const float2* A2 = spA2 + cur * PA2_F2;
        const float* Vb = svp + cur * VP_FLOATS;

        #pragma unroll
        for (int kc = 0; kc < 4; kc++) {
            const int u = kc * 4 + tig;
            uint32_t a[2][4];
            #pragma unroll
            for (int mt = 0; mt < 2; mt++) {
                const int r = warpM * 32 + mt * 16 + gid;
                float2 lo = A2[r * PA2_STRIDE + u];
                float2 hi = A2[(r + 8) * PA2_STRIDE + u];
                a[mt][0] = __float_as_uint(lo.x);
                a[mt][1] = __float_as_uint(hi.x);
                a[mt][2] = __float_as_uint(lo.y);
                a[mt][3] = __float_as_uint(hi.y);
            }
            const float* vrow = Vb + (kc * 4 + tig) * VROW;
            #pragma unroll
            for (int nt = 0; nt < 8; nt++) {
                const int n = warpN * 64 + nt * 8 + gid;
                float2 b = *(const float2*)&vrow[n * 2];
                mma_tf32(acc[0][nt], a[0], __float_as_uint(b.x), __float_as_uint(b.y));
                mma_tf32(acc[1][nt], a[1], __float_as_uint(b.x), __float_as_uint(b.y));
            }
        }

        if (more) produce_P(spA2 + nxt * PA2_F2, aj, dv);
    }

    {
        float z = zacc;
        z += __shfl_xor_sync(0xffffffffu, z, 1);
        z += __shfl_xor_sync(0xffffffffu, z, 2);
        if ((t & 3) == 0) Zp[i0 + pr] = z;
    }

    #pragma unroll
    for (int mt = 0; mt < 2; mt++) {
        const int r0 = warpM * 32 + mt * 16 + gid;
        const int r1 = r0 + 8;
        #pragma unroll
        for (int nt = 0; nt < 8; nt++) {
            const int col = warpN * 64 + nt * 8 + 2 * tig;
            float4 c = acc[mt][nt];
            *(float2*)&Dp[(size_t)(i0 + r0) * DIM + col] = make_float2(c.x, c.y);
            *(float2*)&Dp[(size_t)(i0 + r1) * DIM + col] = make_float2(c.z, c.w);
        }
    }
}

// ---------------------------------------------------------------------------
// out = relu((D0+D1)/Z); optionally emit tf32 copy as next layer's A operand
// ---------------------------------------------------------------------------
__global__ void __launch_bounds__(256) combine_out(float* __restrict__ out,
                                                   float* __restrict__ At,
                                                   int write_at) {
    int idx = blockIdx.x * 256 + threadIdx.x;
    int row = idx >> 6;
    float4 a = ((const float4*)g_Dp[0])[idx];
    float4 b = ((const float4*)g_Dp[1])[idx];
    float z = g_Zp[0][row] + g_Zp[1][row];
    float rz = (z > 0.f) ? 1.f / z : 0.f;
    float4 o;
    o.x = fmaxf((a.x + b.x) * rz, 0.f);
    o.y = fmaxf((a.y + b.y) * rz, 0.f);
    o.z = fmaxf((a.z + b.z) * rz, 0.f);
    o.w = fmaxf((a.w + b.w) * rz, 0.f);
    ((float4*)out)[idx] = o;
    if (write_at)
        ((float4*)At)[idx] = make_float4(tf32r(o.x), tf32r(o.y), tf32r(o.z), tf32r(o.w));
}

// ---------------------------------------------------------------------------
static void run_layer(const int* adj, const float* W,
                      const float* a_src, const float* a_dst, float* out,
                      int write_at) {
    float *At, *Dp, *Zp;
    float2 *Vp, *Wp;
    cudaGetSymbolAddress((void**)&At, g_At);
    cudaGetSymbolAddress((void**)&Wp, g_Wp);
    cudaGetSymbolAddress((void**)&Vp, g_Vp);
    cudaGetSymbolAddress((void**)&Dp, g_Dp);
    cudaGetSymbolAddress((void**)&Zp, g_Zp);

    wpack<<<DIM / BK, 256>>>(W, Wp);
    gemm_tc<<<N_NODES / 64, 256, GSMEM_BYTES>>>(At, Wp, Vp, a_src, a_dst);
    gat_mma<<<dim3(N_NODES / BM, SPLIT), 256, SMEM_BYTES>>>(Vp, adj, Dp, Zp);
    combine_out<<<(N_NODES * DIM / 4) / 256, 256>>>(out, At, write_at);
}

extern "C" void kernel_launch(void* const* d_in, const int* in_sizes, int n_in,
                              void* d_out, int out_size) {
    const float* x      = (const float*)d_in[0];
    const int*   adj    = (const int*)d_in[1];
    const float* W1     = (const float*)d_in[2];
    const float* a1_src = (const float*)d_in[3];
    const float* a1_dst = (const float*)d_in[4];
    const float* W2     = (const float*)d_in[5];
    const float* a2_src = (const float*)d_in[6];
    const float* a2_dst = (const float*)d_in[7];
    float* out = (float*)d_out;

    cudaFuncSetAttribute(gat_mma, cudaFuncAttributeMaxDynamicSharedMemorySize,
                         SMEM_BYTES);
    cudaFuncSetAttribute(gemm_tc, cudaFuncAttributeMaxDynamicSharedMemorySize,
                         GSMEM_BYTES);

    float *h1, *At;
    cudaGetSymbolAddress((void**)&h1, g_h1);
    cudaGetSymbolAddress((void**)&At, g_At);

    apack<<<(N_NODES * DIM / 4) / 256, 256>>>(x, At);
    run_layer(adj, W1, a1_src, a1_dst, h1, /*write_at=*/1);
    run_layer(adj, W2, a2_src, a2_dst, out, /*write_at=*/0);
}

// round 14
// speedup vs baseline: 1.1553x; 1.1553x over previous
#include <cuda_runtime.h>
#include <cstdint>

#define N_NODES 8192
#define DIM 256
#define SPLIT 2
#define KSPAN (N_NODES / SPLIT)   // 4096
#define BK 32
#define NCH (KSPAN / BK)          // 128 iters per CTA
#define BM 64
#define NCHUNK_TOT (N_NODES / BK) // 256 packed V chunks
#define LOG2E 1.4426950408889634f

// ---- device scratch (static only) ----
__device__ float  g_At[N_NODES * DIM];          // tf32-rounded gemm A operand
__device__ float2 g_Wp[(DIM / BK) * 16 * 256];  // packed tf32 W pairs (256 KB)
__device__ float2 g_Vp[NCHUNK_TOT * 16 * 256];  // packed tf32 V pairs (8 MB)
__device__ float  g_h1[N_NODES * DIM];
__device__ float  g_Dp[SPLIT][N_NODES * DIM];   // split-K partial numerators
__device__ float  g_Zp[SPLIT][N_NODES];         // split-K partial Z
__device__ float  g_sL[N_NODES];                // s * log2(e)
__device__ float  g_dL[N_NODES];                // d * log2(e)

__device__ __forceinline__ float tf32r(float x) {
    uint32_t u;
    asm("cvt.rna.tf32.f32 %0, %1;" : "=r"(u) : "f"(x));
    return __uint_as_float(u);
}
__device__ __forceinline__ float ex2(float x) {
    float r;
    asm("ex2.approx.f32 %0, %1;" : "=f"(r) : "f"(x));
    return r;
}
__device__ __forceinline__ void mma_tf32(float4& c, const uint32_t a[4],
                                         uint32_t b0, uint32_t b1) {
    asm volatile(
        "mma.sync.aligned.m16n8k8.row.col.f32.tf32.tf32.f32 "
        "{%0,%1,%2,%3}, {%4,%5,%6,%7}, {%8,%9}, {%0,%1,%2,%3};"
        : "+f"(c.x), "+f"(c.y), "+f"(c.z), "+f"(c.w)
        : "r"(a[0]), "r"(a[1]), "r"(a[2]), "r"(a[3]), "r"(b0), "r"(b1));
}
__device__ __forceinline__ void ldsm_x4(uint32_t& r0, uint32_t& r1,
                                        uint32_t& r2, uint32_t& r3,
                                        uint32_t addr) {
    asm volatile("ldmatrix.sync.aligned.m8n8.x4.shared.b16 {%0,%1,%2,%3}, [%4];"
                 : "=r"(r0), "=r"(r1), "=r"(r2), "=r"(r3) : "r"(addr));
}
__device__ __forceinline__ void cp_async16(uint32_t dst, const void* src) {
    asm volatile("cp.async.cg.shared.global [%0], [%1], 16;" :: "r"(dst), "l"(src));
}

// ---------------------------------------------------------------------------
// apack: tf32-round A operand elementwise (layer-1 input only)
// ---------------------------------------------------------------------------
__global__ void __launch_bounds__(256) apack(const float* __restrict__ A,
                                             float* __restrict__ At) {
    int idx = blockIdx.x * 256 + threadIdx.x;
    float4 v = ((const float4*)A)[idx];
    ((float4*)At)[idx] = make_float4(tf32r(v.x), tf32r(v.y), tf32r(v.z), tf32r(v.w));
}

// ---------------------------------------------------------------------------
// wpack: Wp[(c*16+w)*256+n] = (tf32(W[j0][n]), tf32(W[j0+4][n]))
// ---------------------------------------------------------------------------
__global__ void __launch_bounds__(256) wpack(const float* __restrict__ W,
                                             float2* __restrict__ Wp) {
    const int c = blockIdx.x;
    const int t = threadIdx.x;
    #pragma unroll
    for (int w = 0; w < 16; w++) {
        int j0 = c * 32 + (w >> 2) * 8 + (w & 3);
        float v0 = W[(size_t)j0 * DIM + t];
        float v1 = W[(size_t)(j0 + 4) * DIM + t];
        Wp[(size_t)(c * 16 + w) * 256 + t] = make_float2(tf32r(v0), tf32r(v1));
    }
}

// ---------------------------------------------------------------------------
// Tensor-core GEMM Wh = At @ W, FUSED epilogue (unchanged from R12):
//   parks the 64x256 Wh tile in smem, emits packed Vp + sL/dL directly.
// ---------------------------------------------------------------------------
#define GA_STRIDE 36
#define GA_FLOATS (64 * GA_STRIDE)          // 2304
#define GVROW 520
#define GW_FLOATS (16 * GVROW)              // 8320
#define GMAIN_FLOATS (2 * GA_FLOATS + 2 * GW_FLOATS)   // 21248 floats
#define WS 260                               // epilogue tile stride
#define GSMEM_BYTES ((GMAIN_FLOATS + 2 * 256) * 4 + 16)

__global__ void __launch_bounds__(256, 2) gemm_tc(const float* __restrict__ At,
                                                  const float2* __restrict__ Wp,
                                                  float2* __restrict__ Vp,
                                                  const float* __restrict__ a_src,
                                                  const float* __restrict__ a_dst) {
    extern __shared__ float smem[];
    float* sA = smem;
    float* sW = smem + 2 * GA_FLOATS;
    float* sas = smem + GMAIN_FLOATS;
    float* sad = sas + 256;

    const int t = threadIdx.x;
    const int lane = t & 31;
    const int warp = t >> 5;
    const int warpM = warp >> 2;
    const int warpN = warp & 3;
    const int gid = lane >> 2;
    const int tig = lane & 3;
    const int i0 = blockIdx.x * 64;

    const uint32_t sA_u32 = (uint32_t)__cvta_generic_to_shared(sA);
    const uint32_t sW_u32 = (uint32_t)__cvta_generic_to_shared(sW);

    sas[t] = a_src[t];
    sad[t] = a_dst[t];

    float4 acc[2][8];
    #pragma unroll
    for (int m = 0; m < 2; m++)
        #pragma unroll
        for (int n = 0; n < 8; n++) acc[m][n] = make_float4(0.f, 0.f, 0.f, 0.f);

    auto stage = [&](int buf, int ch) {
        #pragma unroll
        for (int w = 0; w < 2; w++) {
            int qid = t + 256 * w;
            int rp = qid >> 3, u = qid & 7;
            cp_async16(sA_u32 + buf * (GA_FLOATS * 4) + rp * (GA_STRIDE * 4) + u * 16,
                       At + (size_t)(i0 + rp) * DIM + ch * 32 + u * 4);
        }
        const char* gsrc = (const char*)(Wp + (size_t)ch * 16 * 256);
        #pragma unroll
        for (int w = 0; w < 8; w++) {
            int qid = t + 256 * w;
            int rp = qid >> 7;
            int off = (qid & 127) * 16;
            cp_async16(sW_u32 + buf * (GW_FLOATS * 4) + rp * (GVROW * 4) + off,
                       gsrc + qid * 16);
        }
        asm volatile("cp.async.commit_group;" ::: "memory");
    };

    stage(0, 0);

    #pragma unroll
    for (int it = 0; it < 8; ++it) {
        const int cur = it & 1, nxt = cur ^ 1;
        asm volatile("cp.async.wait_group 0;" ::: "memory");
        __syncthreads();
        if (it + 1 < 8) stage(nxt, it + 1);

        const float* A = sA + cur * GA_FLOATS;
        const float* Wb = sW + cur * GW_FLOATS;

        #pragma unroll
        for (int kc = 0; kc < 4; kc++) {
            uint32_t a[2][4];
            #pragma unroll
            for (int mt = 0; mt < 2; mt++) {
                const int r = warpM * 32 + mt * 16 + gid;
                const int c = kc * 8 + tig;
                a[mt][0] = __float_as_uint(A[r * GA_STRIDE + c]);
                a[mt][1] = __float_as_uint(A[(r + 8) * GA_STRIDE + c]);
                a[mt][2] = __float_as_uint(A[r * GA_STRIDE + c + 4]);
                a[mt][3] = __float_as_uint(A[(r + 8) * GA_STRIDE + c + 4]);
            }
            const float* vrow = Wb + (kc * 4 + tig) * GVROW;
            #pragma unroll
            for (int nt = 0; nt < 8; nt++) {
                const int n = warpN * 64 + nt * 8 + gid;
                float2 b = *(const float2*)&vrow[n * 2];
                mma_tf32(acc[0][nt], a[0], __float_as_uint(b.x), __float_as_uint(b.y));
                mma_tf32(acc[1][nt], a[1], __float_as_uint(b.x), __float_as_uint(b.y));
            }
        }
        __syncthreads();
    }

    // ---- epilogue: park tile in smem ----
    float* S = smem;                          // [64][WS]
    #pragma unroll
    for (int mt = 0; mt < 2; mt++) {
        const int r0 = warpM * 32 + mt * 16 + gid;
        const int r1 = r0 + 8;
        #pragma unroll
        for (int nt = 0; nt < 8; nt++) {
            const int col = warpN * 64 + nt * 8 + 2 * tig;
            float4 c = acc[mt][nt];
            S[r0 * WS + col] = c.x; S[r0 * WS + col + 1] = c.y;
            S[r1 * WS + col] = c.z; S[r1 * WS + col + 1] = c.w;
        }
    }
    __syncthreads();

    #pragma unroll
    for (int half = 0; half < 2; half++) {
        const int chunk = (i0 >> 5) + half;
        #pragma unroll
        for (int w = 0; w < 16; w++) {
            int jl = half * 32 + (w >> 2) * 8 + (w & 3);
            float v0 = S[jl * WS + t];
            float v1 = S[(jl + 4) * WS + t];
            Vp[(size_t)(chunk * 16 + w) * 256 + t] = make_float2(tf32r(v0), tf32r(v1));
        }
    }

    #pragma unroll
    for (int rr = 0; rr < 8; rr++) {
        const int rl = warp * 8 + rr;
        float ps = 0.f, pd = 0.f;
        #pragma unroll
        for (int c = lane; c < 256; c += 32) {
            float v = S[rl * WS + c];
            ps = fmaf(v, sas[c], ps);
            pd = fmaf(v, sad[c], pd);
        }
        #pragma unroll
        for (int o = 16; o > 0; o >>= 1) {
            ps += __shfl_down_sync(0xffffffffu, ps, o);
            pd += __shfl_down_sync(0xffffffffu, pd, o);
        }
        if (lane == 0) {
            g_sL[i0 + rl] = ps * LOG2E;
            g_dL[i0 + rl] = pd * LOG2E;
        }
    }
}

// ---------------------------------------------------------------------------
// Fused attention * Wh — R12 champion config with ONE change:
// A fragments loaded via ldmatrix.m8n8.x4 (1 LDSM replaces 4 LDS.32).
// P tile layout/producer identical to R12 (stride 36 floats, STS.128 x2).
// int4 adj, ex2 P, split-K=2, 8 warps (2M x 4N), 2 CTAs/SM.
// ---------------------------------------------------------------------------
#define PA_STRIDE 36
#define PA_FLOATS (64 * PA_STRIDE)          // 2304
#define VROW 520                            // 512 data + 8 pad (==8 mod 32)
#define VP_FLOATS (16 * VROW)               // 8320
#define SMEM_FLOATS (2 * PA_FLOATS + 2 * VP_FLOATS)
#define SMEM_BYTES (SMEM_FLOATS * 4 + 16)

__global__ void __launch_bounds__(256, 2) gat_mma(const float2* __restrict__ Vp,
                                                  const int* __restrict__ adj,
                                                  float* __restrict__ Dp,
                                                  float* __restrict__ Zp) {
    extern __shared__ float smem[];
    float* spA = smem;                      // [2][PA_FLOATS]
    float* svp = smem + 2 * PA_FLOATS;      // [2][VP_FLOATS]

    const int t = threadIdx.x;
    const int lane = t & 31;
    const int warp = t >> 5;
    const int warpM = warp >> 2;            // 0..1
    const int warpN = warp & 3;             // 0..3
    const int gid = lane >> 2;              // 0..7
    const int tig = lane & 3;               // 0..3
    const int i0 = blockIdx.x * BM;
    const int split = blockIdx.y;
    const int ch0 = split * (NCHUNK_TOT / SPLIT);

    Dp += (size_t)split * N_NODES * DIM;
    Zp += (size_t)split * N_NODES;

    const int pr = t >> 2;
    const int kb = (t & 3) * 8;
    const float sL_r = g_sL[i0 + pr];
    const int* adjrow = adj + (size_t)(i0 + pr) * N_NODES + split * KSPAN;
    const float* dbase = g_dL + split * KSPAN;

    float4 acc[2][8];
    #pragma unroll
    for (int m = 0; m < 2; m++)
        #pragma unroll
        for (int n = 0; n < 8; n++) acc[m][n] = make_float4(0.f, 0.f, 0.f, 0.f);
    float zacc = 0.f;

    const uint32_t sv_u32 = (uint32_t)__cvta_generic_to_shared(svp);
    const uint32_t spA_u32 = (uint32_t)__cvta_generic_to_shared(spA);

    // ldmatrix per-lane row/col assignment (same for both m-tiles):
    //   matrices: {rows r..r+7, cols c..c+3}, {rows r+8..r+15, same},
    //             {rows r..r+7, cols c+4..c+7}, {rows r+8..r+15, same}
    const int lrow = warpM * 32 + (lane & 15);      // + mt*16
    const int lcol = (lane >> 4) * 4;               // 0 or 4
    const uint32_t abase0 = spA_u32 + (lrow * PA_STRIDE + lcol) * 4;
    const uint32_t abase1 = abase0 + 16 * PA_STRIDE * 4;

    auto produce_P = [&](float* buf, const int4 aj[2], const float4 dv[2]) {
        const float dj[8] = {dv[0].x, dv[0].y, dv[0].z, dv[0].w,
                             dv[1].x, dv[1].y, dv[1].z, dv[1].w};
        const int mk[8] = {aj[0].x, aj[0].y, aj[0].z, aj[0].w,
                           aj[1].x, aj[1].y, aj[1].z, aj[1].w};
        float p[8];
        #pragma unroll
        for (int q = 0; q < 8; q++) {
            float t2 = sL_r + dj[q];
            float e = ex2(fmaxf(t2, 0.2f * t2));
            p[q] = mk[q] ? e : 0.f;
        }
        zacc += ((p[0] + p[1]) + (p[2] + p[3])) + ((p[4] + p[5]) + (p[6] + p[7]));
        float* dst = buf + pr * PA_STRIDE + kb;
        *(float4*)dst = make_float4(tf32r(p[0]), tf32r(p[1]), tf32r(p[2]), tf32r(p[3]));
        *(float4*)(dst + 4) = make_float4(tf32r(p[4]), tf32r(p[5]), tf32r(p[6]), tf32r(p[7]));
    };

    auto issue_V = [&](int buf, int chunk) {
        const char* gsrc = (const char*)(Vp + (size_t)chunk * 16 * 256);
        uint32_t base = sv_u32 + buf * (VP_FLOATS * 4);
        #pragma unroll
        for (int w = 0; w < 8; w++) {
            int qid = t + 256 * w;
            int rp = qid >> 7;
            int off = (qid & 127) * 16;
            cp_async16(base + rp * (VROW * 4) + off, gsrc + qid * 16);
        }
        asm volatile("cp.async.commit_group;" ::: "memory");
    };

    {
        int4 aj[2]; float4 dv[2];
        aj[0] = *(const int4*)&adjrow[kb];
        aj[1] = *(const int4*)&adjrow[kb + 4];
        dv[0] = *(const float4*)&dbase[kb];
        dv[1] = *(const float4*)&dbase[kb + 4];
        produce_P(spA, aj, dv);
        issue_V(0, ch0);
    }

    for (int it = 0; it < NCH; ++it) {
        const int cur = it & 1, nxt = cur ^ 1;
        const bool more = (it + 1 < NCH);

        int4 aj[2]; float4 dv[2];
        if (more) {
            const int jc = (it + 1) * BK;
            aj[0] = *(const int4*)&adjrow[jc + kb];
            aj[1] = *(const int4*)&adjrow[jc + kb + 4];
            dv[0] = *(const float4*)&dbase[jc + kb];
            dv[1] = *(const float4*)&dbase[jc + kb + 4];
        }

        asm volatile("cp.async.wait_group 0;" ::: "memory");
        __syncthreads();

        if (more) issue_V(nxt, ch0 + it + 1);

        const uint32_t abufoff = (uint32_t)(cur * PA_FLOATS * 4);
        const float* Vb = svp + cur * VP_FLOATS;

        #pragma unroll
        for (int kc = 0; kc < 4; kc++) {
            uint32_t a[2][4];
            ldsm_x4(a[0][0], a[0][1], a[0][2], a[0][3], abase0 + abufoff + kc * 32);
            ldsm_x4(a[1][0], a[1][1], a[1][2], a[1][3], abase1 + abufoff + kc * 32);
            const float* vrow = Vb + (kc * 4 + tig) * VROW;
            #pragma unroll
            for (int nt = 0; nt < 8; nt++) {
                const int n = warpN * 64 + nt * 8 + gid;
                float2 b = *(const float2*)&vrow[n * 2];
                mma_tf32(acc[0][nt], a[0], __float_as_uint(b.x), __float_as_uint(b.y));
                mma_tf32(acc[1][nt], a[1], __float_as_uint(b.x), __float_as_uint(b.y));
            }
        }

        if (more) produce_P(spA + nxt * PA_FLOATS, aj, dv);
    }

    {
        float z = zacc;
        z += __shfl_xor_sync(0xffffffffu, z, 1);
        z += __shfl_xor_sync(0xffffffffu, z, 2);
        if ((t & 3) == 0) Zp[i0 + pr] = z;
    }

    #pragma unroll
    for (int mt = 0; mt < 2; mt++) {
        const int r0 = warpM * 32 + mt * 16 + gid;
        const int r1 = r0 + 8;
        #pragma unroll
        for (int nt = 0; nt < 8; nt++) {
            const int col = warpN * 64 + nt * 8 + 2 * tig;
            float4 c = acc[mt][nt];
            *(float2*)&Dp[(size_t)(i0 + r0) * DIM + col] = make_float2(c.x, c.y);
            *(float2*)&Dp[(size_t)(i0 + r1) * DIM + col] = make_float2(c.z, c.w);
        }
    }
}

// ---------------------------------------------------------------------------
// out = relu((D0+D1)/Z); optionally emit tf32 copy as next layer's A operand
// ---------------------------------------------------------------------------
__global__ void __launch_bounds__(256) combine_out(float* __restrict__ out,
                                                   float* __restrict__ At,
                                                   int write_at) {
    int idx = blockIdx.x * 256 + threadIdx.x;
    int row = idx >> 6;
    float4 a = ((const float4*)g_Dp[0])[idx];
    float4 b = ((const float4*)g_Dp[1])[idx];
    float z = g_Zp[0][row] + g_Zp[1][row];
    float rz = (z > 0.f) ? 1.f / z : 0.f;
    float4 o;
    o.x = fmaxf((a.x + b.x) * rz, 0.f);
    o.y = fmaxf((a.y + b.y) * rz, 0.f);
    o.z = fmaxf((a.z + b.z) * rz, 0.f);
    o.w = fmaxf((a.w + b.w) * rz, 0.f);
    ((float4*)out)[idx] = o;
    if (write_at)
        ((float4*)At)[idx] = make_float4(tf32r(o.x), tf32r(o.y), tf32r(o.z), tf32r(o.w));
}

// ---------------------------------------------------------------------------
static void run_layer(const int* adj, const float* W,
                      const float* a_src, const float* a_dst, float* out,
                      int write_at) {
    float *At, *Dp, *Zp;
    float2 *Vp, *Wp;
    cudaGetSymbolAddress((void**)&At, g_At);
    cudaGetSymbolAddress((void**)&Wp, g_Wp);
    cudaGetSymbolAddress((void**)&Vp, g_Vp);
    cudaGetSymbolAddress((void**)&Dp, g_Dp);
    cudaGetSymbolAddress((void**)&Zp, g_Zp);

    wpack<<<DIM / BK, 256>>>(W, Wp);
    gemm_tc<<<N_NODES / 64, 256, GSMEM_BYTES>>>(At, Wp, Vp, a_src, a_dst);
    gat_mma<<<dim3(N_NODES / BM, SPLIT), 256, SMEM_BYTES>>>(Vp, adj, Dp, Zp);
    combine_out<<<(N_NODES * DIM / 4) / 256, 256>>>(out, At, write_at);
}

extern "C" void kernel_launch(void* const* d_in, const int* in_sizes, int n_in,
                              void* d_out, int out_size) {
    const float* x      = (const float*)d_in[0];
    const int*   adj    = (const int*)d_in[1];
    const float* W1     = (const float*)d_in[2];
    const float* a1_src = (const float*)d_in[3];
    const float* a1_dst = (const float*)d_in[4];
    const float* W2     = (const float*)d_in[5];
    const float* a2_src = (const float*)d_in[6];
    const float* a2_dst = (const float*)d_in[7];
    float* out = (float*)d_out;

    cudaFuncSetAttribute(gat_mma, cudaFuncAttributeMaxDynamicSharedMemorySize,
                         SMEM_BYTES);
    cudaFuncSetAttribute(gemm_tc, cudaFuncAttributeMaxDynamicSharedMemorySize,
                         GSMEM_BYTES);

    float *h1, *At;
    cudaGetSymbolAddress((void**)&h1, g_h1);
    cudaGetSymbolAddress((void**)&At, g_At);

    apack<<<(N_NODES * DIM / 4) / 256, 256>>>(x, At);
    run_layer(adj, W1, a1_src, a1_dst, h1, /*write_at=*/1);
    run_layer(adj, W2, a2_src, a2_dst, out, /*write_at=*/0);
}

// round 16
// speedup vs baseline: 1.1859x; 1.0265x over previous
#include <cuda_runtime.h>
#include <cstdint>

#define N_NODES 8192
#define DIM 256
#define SPLIT 4
#define KSPAN (N_NODES / SPLIT)   // 2048
#define BK 32
#define NCH (KSPAN / BK)          // 64 iters per CTA
#define BM 64
#define NCHUNK_TOT (N_NODES / BK) // 256 packed V chunks
#define LOG2E 1.4426950408889634f

// ---- device scratch (static only) ----
__device__ float  g_At[N_NODES * DIM];          // tf32-rounded gemm A operand
__device__ float2 g_Wp[(DIM / BK) * 16 * 256];  // packed tf32 W pairs (256 KB)
__device__ float2 g_Vp[NCHUNK_TOT * 16 * 256];  // packed tf32 V pairs (8 MB)
__device__ float  g_h1[N_NODES * DIM];
__device__ float  g_Dp[SPLIT][N_NODES * DIM];   // split-K partial numerators
__device__ float  g_Zp[SPLIT][N_NODES];         // split-K partial Z
__device__ float  g_sL[N_NODES];                // s * log2(e)
__device__ float  g_dL[N_NODES];                // d * log2(e)

__device__ __forceinline__ float tf32r(float x) {
    uint32_t u;
    asm("cvt.rna.tf32.f32 %0, %1;" : "=r"(u) : "f"(x));
    return __uint_as_float(u);
}
__device__ __forceinline__ float ex2(float x) {
    float r;
    asm("ex2.approx.f32 %0, %1;" : "=f"(r) : "f"(x));
    return r;
}
__device__ __forceinline__ void mma_tf32(float4& c, const uint32_t a[4],
                                         uint32_t b0, uint32_t b1) {
    asm volatile(
        "mma.sync.aligned.m16n8k8.row.col.f32.tf32.tf32.f32 "
        "{%0,%1,%2,%3}, {%4,%5,%6,%7}, {%8,%9}, {%0,%1,%2,%3};"
        : "+f"(c.x), "+f"(c.y), "+f"(c.z), "+f"(c.w)
        : "r"(a[0]), "r"(a[1]), "r"(a[2]), "r"(a[3]), "r"(b0), "r"(b1));
}
__device__ __forceinline__ void ldsm_x4(uint32_t& r0, uint32_t& r1,
                                        uint32_t& r2, uint32_t& r3,
                                        uint32_t addr) {
    asm volatile("ldmatrix.sync.aligned.m8n8.x4.shared.b16 {%0,%1,%2,%3}, [%4];"
                 : "=r"(r0), "=r"(r1), "=r"(r2), "=r"(r3) : "r"(addr));
}
__device__ __forceinline__ void cp_async16(uint32_t dst, const void* src) {
    asm volatile("cp.async.cg.shared.global [%0], [%1], 16;" :: "r"(dst), "l"(src));
}

// ---------------------------------------------------------------------------
// apack: tf32-round A operand elementwise (layer-1 input only)
// ---------------------------------------------------------------------------
__global__ void __launch_bounds__(256) apack(const float* __restrict__ A,
                                             float* __restrict__ At) {
    int idx = blockIdx.x * 256 + threadIdx.x;
    float4 v = ((const float4*)A)[idx];
    ((float4*)At)[idx] = make_float4(tf32r(v.x), tf32r(v.y), tf32r(v.z), tf32r(v.w));
}

// ---------------------------------------------------------------------------
// wpack: Wp[(c*16+w)*256+n] = (tf32(W[j0][n]), tf32(W[j0+4][n]))
// ---------------------------------------------------------------------------
__global__ void __launch_bounds__(256) wpack(const float* __restrict__ W,
                                             float2* __restrict__ Wp) {
    const int c = blockIdx.x;
    const int t = threadIdx.x;
    #pragma unroll
    for (int w = 0; w < 16; w++) {
        int j0 = c * 32 + (w >> 2) * 8 + (w & 3);
        float v0 = W[(size_t)j0 * DIM + t];
        float v1 = W[(size_t)(j0 + 4) * DIM + t];
        Wp[(size_t)(c * 16 + w) * 256 + t] = make_float2(tf32r(v0), tf32r(v1));
    }
}

// ---------------------------------------------------------------------------
// Tensor-core GEMM Wh = At @ W, FUSED epilogue:
//   parks the 64x256 Wh tile in smem, emits packed Vp + sL/dL directly.
// ---------------------------------------------------------------------------
#define GA_STRIDE 36
#define GA_FLOATS (64 * GA_STRIDE)          // 2304
#define GVROW 520
#define GW_FLOATS (16 * GVROW)              // 8320
#define GMAIN_FLOATS (2 * GA_FLOATS + 2 * GW_FLOATS)   // 21248 floats
#define WS 260                               // epilogue tile stride
#define GSMEM_BYTES ((GMAIN_FLOATS + 2 * 256) * 4 + 16)

__global__ void __launch_bounds__(256, 2) gemm_tc(const float* __restrict__ At,
                                                  const float2* __restrict__ Wp,
                                                  float2* __restrict__ Vp,
                                                  const float* __restrict__ a_src,
                                                  const float* __restrict__ a_dst) {
    extern __shared__ float smem[];
    float* sA = smem;
    float* sW = smem + 2 * GA_FLOATS;
    float* sas = smem + GMAIN_FLOATS;
    float* sad = sas + 256;

    const int t = threadIdx.x;
    const int lane = t & 31;
    const int warp = t >> 5;
    const int warpM = warp >> 2;
    const int warpN = warp & 3;
    const int gid = lane >> 2;
    const int tig = lane & 3;
    const int i0 = blockIdx.x * 64;

    const uint32_t sA_u32 = (uint32_t)__cvta_generic_to_shared(sA);
    const uint32_t sW_u32 = (uint32_t)__cvta_generic_to_shared(sW);

    sas[t] = a_src[t];
    sad[t] = a_dst[t];

    float4 acc[2][8];
    #pragma unroll
    for (int m = 0; m < 2; m++)
        #pragma unroll
        for (int n = 0; n < 8; n++) acc[m][n] = make_float4(0.f, 0.f, 0.f, 0.f);

    auto stage = [&](int buf, int ch) {
        #pragma unroll
        for (int w = 0; w < 2; w++) {
            int qid = t + 256 * w;
            int rp = qid >> 3, u = qid & 7;
            cp_async16(sA_u32 + buf * (GA_FLOATS * 4) + rp * (GA_STRIDE * 4) + u * 16,
                       At + (size_t)(i0 + rp) * DIM + ch * 32 + u * 4);
        }
        const char* gsrc = (const char*)(Wp + (size_t)ch * 16 * 256);
        #pragma unroll
        for (int w = 0; w < 8; w++) {
            int qid = t + 256 * w;
            int rp = qid >> 7;
            int off = (qid & 127) * 16;
            cp_async16(sW_u32 + buf * (GW_FLOATS * 4) + rp * (GVROW * 4) + off,
                       gsrc + qid * 16);
        }
        asm volatile("cp.async.commit_group;" ::: "memory");
    };

    stage(0, 0);

    #pragma unroll
    for (int it = 0; it < 8; ++it) {
        const int cur = it & 1, nxt = cur ^ 1;
        asm volatile("cp.async.wait_group 0;" ::: "memory");
        __syncthreads();
        if (it + 1 < 8) stage(nxt, it + 1);

        const float* A = sA + cur * GA_FLOATS;
        const float* Wb = sW + cur * GW_FLOATS;

        #pragma unroll
        for (int kc = 0; kc < 4; kc++) {
            uint32_t a[2][4];
            #pragma unroll
            for (int mt = 0; mt < 2; mt++) {
                const int r = warpM * 32 + mt * 16 + gid;
                const int c = kc * 8 + tig;
                a[mt][0] = __float_as_uint(A[r * GA_STRIDE + c]);
                a[mt][1] = __float_as_uint(A[(r + 8) * GA_STRIDE + c]);
                a[mt][2] = __float_as_uint(A[r * GA_STRIDE + c + 4]);
                a[mt][3] = __float_as_uint(A[(r + 8) * GA_STRIDE + c + 4]);
            }
            const float* vrow = Wb + (kc * 4 + tig) * GVROW;
            #pragma unroll
            for (int nt = 0; nt < 8; nt++) {
                const int n = warpN * 64 + nt * 8 + gid;
                float2 b = *(const float2*)&vrow[n * 2];
                mma_tf32(acc[0][nt], a[0], __float_as_uint(b.x), __float_as_uint(b.y));
                mma_tf32(acc[1][nt], a[1], __float_as_uint(b.x), __float_as_uint(b.y));
            }
        }
        __syncthreads();
    }

    // ---- epilogue: park tile in smem ----
    float* S = smem;                          // [64][WS]
    #pragma unroll
    for (int mt = 0; mt < 2; mt++) {
        const int r0 = warpM * 32 + mt * 16 + gid;
        const int r1 = r0 + 8;
        #pragma unroll
        for (int nt = 0; nt < 8; nt++) {
            const int col = warpN * 64 + nt * 8 + 2 * tig;
            float4 c = acc[mt][nt];
            S[r0 * WS + col] = c.x; S[r0 * WS + col + 1] = c.y;
            S[r1 * WS + col] = c.z; S[r1 * WS + col + 1] = c.w;
        }
    }
    __syncthreads();

    #pragma unroll
    for (int half = 0; half < 2; half++) {
        const int chunk = (i0 >> 5) + half;
        #pragma unroll
        for (int w = 0; w < 16; w++) {
            int jl = half * 32 + (w >> 2) * 8 + (w & 3);
            float v0 = S[jl * WS + t];
            float v1 = S[(jl + 4) * WS + t];
            Vp[(size_t)(chunk * 16 + w) * 256 + t] = make_float2(tf32r(v0), tf32r(v1));
        }
    }

    #pragma unroll
    for (int rr = 0; rr < 8; rr++) {
        const int rl = warp * 8 + rr;
        float ps = 0.f, pd = 0.f;
        #pragma unroll
        for (int c = lane; c < 256; c += 32) {
            float v = S[rl * WS + c];
            ps = fmaf(v, sas[c], ps);
            pd = fmaf(v, sad[c], pd);
        }
        #pragma unroll
        for (int o = 16; o > 0; o >>= 1) {
            ps += __shfl_down_sync(0xffffffffu, ps, o);
            pd += __shfl_down_sync(0xffffffffu, pd, o);
        }
        if (lane == 0) {
            g_sL[i0 + rl] = ps * LOG2E;
            g_dL[i0 + rl] = pd * LOG2E;
        }
    }
}

// ---------------------------------------------------------------------------
// Fused attention * Wh — R14 config (LDSM A-fragments), SPLIT-K = 4 for
// CTA load balance: grid (128, 4) = 512 half-size CTAs over 148 SMs.
// int4 adj, ex2 P, 8 warps (2M x 4N), 2 CTAs/SM.
// ---------------------------------------------------------------------------
#define PA_STRIDE 36
#define PA_FLOATS (64 * PA_STRIDE)          // 2304
#define VROW 520                            // 512 data + 8 pad (==8 mod 32)
#define VP_FLOATS (16 * VROW)               // 8320
#define SMEM_FLOATS (2 * PA_FLOATS + 2 * VP_FLOATS)
#define SMEM_BYTES (SMEM_FLOATS * 4 + 16)

__global__ void __launch_bounds__(256, 2) gat_mma(const float2* __restrict__ Vp,
                                                  const int* __restrict__ adj,
                                                  float* __restrict__ Dp,
                                                  float* __restrict__ Zp) {
    extern __shared__ float smem[];
    float* spA = smem;                      // [2][PA_FLOATS]
    float* svp = smem + 2 * PA_FLOATS;      // [2][VP_FLOATS]

    const int t = threadIdx.x;
    const int lane = t & 31;
    const int warp = t >> 5;
    const int warpM = warp >> 2;            // 0..1
    const int warpN = warp & 3;             // 0..3
    const int gid = lane >> 2;              // 0..7
    const int tig = lane & 3;               // 0..3
    const int i0 = blockIdx.x * BM;
    const int split = blockIdx.y;
    const int ch0 = split * (NCHUNK_TOT / SPLIT);

    Dp += (size_t)split * N_NODES * DIM;
    Zp += (size_t)split * N_NODES;

    const int pr = t >> 2;
    const int kb = (t & 3) * 8;
    const float sL_r = g_sL[i0 + pr];
    const int* adjrow = adj + (size_t)(i0 + pr) * N_NODES + split * KSPAN;
    const float* dbase = g_dL + split * KSPAN;

    float4 acc[2][8];
    #pragma unroll
    for (int m = 0; m < 2; m++)
        #pragma unroll
        for (int n = 0; n < 8; n++) acc[m][n] = make_float4(0.f, 0.f, 0.f, 0.f);
    float zacc = 0.f;

    const uint32_t sv_u32 = (uint32_t)__cvta_generic_to_shared(svp);
    const uint32_t spA_u32 = (uint32_t)__cvta_generic_to_shared(spA);

    const int lrow = warpM * 32 + (lane & 15);      // + mt*16
    const int lcol = (lane >> 4) * 4;               // 0 or 4
    const uint32_t abase0 = spA_u32 + (lrow * PA_STRIDE + lcol) * 4;
    const uint32_t abase1 = abase0 + 16 * PA_STRIDE * 4;

    auto produce_P = [&](float* buf, const int4 aj[2], const float4 dv[2]) {
        const float dj[8] = {dv[0].x, dv[0].y, dv[0].z, dv[0].w,
                             dv[1].x, dv[1].y, dv[1].z, dv[1].w};
        const int mk[8] = {aj[0].x, aj[0].y, aj[0].z, aj[0].w,
                           aj[1].x, aj[1].y, aj[1].z, aj[1].w};
        float p[8];
        #pragma unroll
        for (int q = 0; q < 8; q++) {
            float t2 = sL_r + dj[q];
            float e = ex2(fmaxf(t2, 0.2f * t2));
            p[q] = mk[q] ? e : 0.f;
        }
        zacc += ((p[0] + p[1]) + (p[2] + p[3])) + ((p[4] + p[5]) + (p[6] + p[7]));
        float* dst = buf + pr * PA_STRIDE + kb;
        *(float4*)dst = make_float4(tf32r(p[0]), tf32r(p[1]), tf32r(p[2]), tf32r(p[3]));
        *(float4*)(dst + 4) = make_float4(tf32r(p[4]), tf32r(p[5]), tf32r(p[6]), tf32r(p[7]));
    };

    auto issue_V = [&](int buf, int chunk) {
        const char* gsrc = (const char*)(Vp + (size_t)chunk * 16 * 256);
        uint32_t base = sv_u32 + buf * (VP_FLOATS * 4);
        #pragma unroll
        for (int w = 0; w < 8; w++) {
            int qid = t + 256 * w;
            int rp = qid >> 7;
            int off = (qid & 127) * 16;
            cp_async16(base + rp * (VROW * 4) + off, gsrc + qid * 16);
        }
        asm volatile("cp.async.commit_group;" ::: "memory");
    };

    {
        int4 aj[2]; float4 dv[2];
        aj[0] = *(const int4*)&adjrow[kb];
        aj[1] = *(const int4*)&adjrow[kb + 4];
        dv[0] = *(const float4*)&dbase[kb];
        dv[1] = *(const float4*)&dbase[kb + 4];
        produce_P(spA, aj, dv);
        issue_V(0, ch0);
    }

    for (int it = 0; it < NCH; ++it) {
        const int cur = it & 1, nxt = cur ^ 1;
        const bool more = (it + 1 < NCH);

        int4 aj[2]; float4 dv[2];
        if (more) {
            const int jc = (it + 1) * BK;
            aj[0] = *(const int4*)&adjrow[jc + kb];
            aj[1] = *(const int4*)&adjrow[jc + kb + 4];
            dv[0] = *(const float4*)&dbase[jc + kb];
            dv[1] = *(const float4*)&dbase[jc + kb + 4];
        }

        asm volatile("cp.async.wait_group 0;" ::: "memory");
        __syncthreads();

        if (more) issue_V(nxt, ch0 + it + 1);

        const uint32_t abufoff = (uint32_t)(cur * PA_FLOATS * 4);
        const float* Vb = svp + cur * VP_FLOATS;

        #pragma unroll
        for (int kc = 0; kc < 4; kc++) {
            uint32_t a[2][4];
            ldsm_x4(a[0][0], a[0][1], a[0][2], a[0][3], abase0 + abufoff + kc * 32);
            ldsm_x4(a[1][0], a[1][1], a[1][2], a[1][3], abase1 + abufoff + kc * 32);
            const float* vrow = Vb + (kc * 4 + tig) * VROW;
            #pragma unroll
            for (int nt = 0; nt < 8; nt++) {
                const int n = warpN * 64 + nt * 8 + gid;
                float2 b = *(const float2*)&vrow[n * 2];
                mma_tf32(acc[0][nt], a[0], __float_as_uint(b.x), __float_as_uint(b.y));
                mma_tf32(acc[1][nt], a[1], __float_as_uint(b.x), __float_as_uint(b.y));
            }
        }

        if (more) produce_P(spA + nxt * PA_FLOATS, aj, dv);
    }

    {
        float z = zacc;
        z += __shfl_xor_sync(0xffffffffu, z, 1);
        z += __shfl_xor_sync(0xffffffffu, z, 2);
        if ((t & 3) == 0) Zp[i0 + pr] = z;
    }

    #pragma unroll
    for (int mt = 0; mt < 2; mt++) {
        const int r0 = warpM * 32 + mt * 16 + gid;
        const int r1 = r0 + 8;
        #pragma unroll
        for (int nt = 0; nt < 8; nt++) {
            const int col = warpN * 64 + nt * 8 + 2 * tig;
            float4 c = acc[mt][nt];
            *(float2*)&Dp[(size_t)(i0 + r0) * DIM + col] = make_float2(c.x, c.y);
            *(float2*)&Dp[(size_t)(i0 + r1) * DIM + col] = make_float2(c.z, c.w);
        }
    }
}

// ---------------------------------------------------------------------------
// out = relu((sum_k Dk)/(sum_k Zk)); optionally emit tf32 copy for next layer
// ---------------------------------------------------------------------------
__global__ void __launch_bounds__(256) combine_out(float* __restrict__ out,
                                                   float* __restrict__ At,
                                                   int write_at) {
    int idx = blockIdx.x * 256 + threadIdx.x;
    int row = idx >> 6;
    float4 a0 = ((const float4*)g_Dp[0])[idx];
    float4 a1 = ((const float4*)g_Dp[1])[idx];
    float4 a2 = ((const float4*)g_Dp[2])[idx];
    float4 a3 = ((const float4*)g_Dp[3])[idx];
    float z = (g_Zp[0][row] + g_Zp[1][row]) + (g_Zp[2][row] + g_Zp[3][row]);
    float rz = (z > 0.f) ? 1.f / z : 0.f;
    float4 o;
    o.x = fmaxf(((a0.x + a1.x) + (a2.x + a3.x)) * rz, 0.f);
    o.y = fmaxf(((a0.y + a1.y) + (a2.y + a3.y)) * rz, 0.f);
    o.z = fmaxf(((a0.z + a1.z) + (a2.z + a3.z)) * rz, 0.f);
    o.w = fmaxf(((a0.w + a1.w) + (a2.w + a3.w)) * rz, 0.f);
    ((float4*)out)[idx] = o;
    if (write_at)
        ((float4*)At)[idx] = make_float4(tf32r(o.x), tf32r(o.y), tf32r(o.z), tf32r(o.w));
}

// ---------------------------------------------------------------------------
static void run_layer(const int* adj, const float* W,
                      const float* a_src, const float* a_dst, float* out,
                      int write_at) {
    float *At, *Dp, *Zp;
    float2 *Vp, *Wp;
    cudaGetSymbolAddress((void**)&At, g_At);
    cudaGetSymbolAddress((void**)&Wp, g_Wp);
    cudaGetSymbolAddress((void**)&Vp, g_Vp);
    cudaGetSymbolAddress((void**)&Dp, g_Dp);
    cudaGetSymbolAddress((void**)&Zp, g_Zp);

    wpack<<<DIM / BK, 256>>>(W, Wp);
    gemm_tc<<<N_NODES / 64, 256, GSMEM_BYTES>>>(At, Wp, Vp, a_src, a_dst);
    gat_mma<<<dim3(N_NODES / BM, SPLIT), 256, SMEM_BYTES>>>(Vp, adj, Dp, Zp);
    combine_out<<<(N_NODES * DIM / 4) / 256, 256>>>(out, At, write_at);
}

extern "C" void kernel_launch(void* const* d_in, const int* in_sizes, int n_in,
                              void* d_out, int out_size) {
    const float* x      = (const float*)d_in[0];
    const int*   adj    = (const int*)d_in[1];
    const float* W1     = (const float*)d_in[2];
    const float* a1_src = (const float*)d_in[3];
    const float* a1_dst = (const float*)d_in[4];
    const float* W2     = (const float*)d_in[5];
    const float* a2_src = (const float*)d_in[6];
    const float* a2_dst = (const float*)d_in[7];
    float* out = (float*)d_out;

    cudaFuncSetAttribute(gat_mma, cudaFuncAttributeMaxDynamicSharedMemorySize,
                         SMEM_BYTES);
    cudaFuncSetAttribute(gemm_tc, cudaFuncAttributeMaxDynamicSharedMemorySize,
                         GSMEM_BYTES);

    float *h1, *At;
    cudaGetSymbolAddress((void**)&h1, g_h1);
    cudaGetSymbolAddress((void**)&At, g_At);

    apack<<<(N_NODES * DIM / 4) / 256, 256>>>(x, At);
    run_layer(adj, W1, a1_src, a1_dst, h1, /*write_at=*/1);
    run_layer(adj, W2, a2_src, a2_dst, out, /*write_at=*/0);
}